// round 10
// baseline (speedup 1.0000x reference)
#include <cuda_runtime.h>
#include <cstdint>

// CovNet_3058016715001 — binarized-weight MLP via int8 dual-plane mma.sync.
// Round 10: round-7 champion + explicit fragment double-buffering:
// all 12 LDSMs of a chunk issued up-front, IMMAs scheduled H-then-L per
// ks-block so ks1 runs with zero LDSM wait.
//   h   = clip(x @ sign(W1)^T + b1, -1, 1)     x:[8192,784] W1:[4096,784]
//   out = h @ W2^T + b2                        W2:[10,4096]  out:[8192,10]

#define BATCH 8192
#define IN_F  784
#define KP8   832           // 13 * 64
#define HID   4096
#define NOUT  10

#define BM 64
#define BN 128
#define BK 64
#define NCH 13

#define OFF_ALO 4096
#define OFF_BW  8192
#define STAGE   16384       // Ahi(4K) Alo(4K) B(8K)

// dynamic smem map: 4 stages, then W2s/b1s
#define OFF_W2   65536
#define OFF_B1   70656
#define SMEM_REQ (71168 + 128)

#define SCALE_S 4096.0f
#define INV_S   (1.0f / 4096.0f)

static __device__ char g_Xh8[(size_t)BATCH * KP8];
static __device__ char g_Xl8[(size_t)BATCH * KP8];
static __device__ char g_W8 [(size_t)HID * KP8];

// ---------------------------------------------------------------- helpers
__device__ __forceinline__ uint32_t smem_u32(const void* p) {
    return (uint32_t)__cvta_generic_to_shared(p);
}

#define CP_ASYNC16(s, g) \
    asm volatile("cp.async.cg.shared.global [%0], [%1], 16;" :: "r"(s), "l"(g))
#define CP_COMMIT() asm volatile("cp.async.commit_group;")
#define CP_WAIT(n)  asm volatile("cp.async.wait_group %0;" :: "n"(n) : "memory")

__device__ __forceinline__ void ldm_x4(uint32_t& r0, uint32_t& r1, uint32_t& r2,
                                       uint32_t& r3, uint32_t addr) {
    asm volatile("ldmatrix.sync.aligned.m8n8.x4.shared.b16 {%0,%1,%2,%3}, [%4];"
                 : "=r"(r0), "=r"(r1), "=r"(r2), "=r"(r3) : "r"(addr));
}

#define MMA_S8(d, a, b) \
    asm volatile("mma.sync.aligned.m16n8k32.row.col.s32.s8.s8.s32 " \
        "{%0,%1,%2,%3}, {%4,%5,%6,%7}, {%8,%9}, {%0,%1,%2,%3};" \
        : "+r"((d)[0]), "+r"((d)[1]), "+r"((d)[2]), "+r"((d)[3]) \
        : "r"((a)[0]), "r"((a)[1]), "r"((a)[2]), "r"((a)[3]), \
          "r"((b)[0]), "r"((b)[1]))

__device__ __forceinline__ uint32_t sw128(uint32_t flat) {
    return flat ^ ((flat >> 3) & 0x70);
}

// ---------------------------------------------------------------- prep
__global__ void init_out_kernel(float* __restrict__ out, const float* __restrict__ b2) {
    int i = blockIdx.x * blockDim.x + threadIdx.x;
    if (i < BATCH * NOUT) out[i] = b2[i % NOUT];
}

__global__ void conv_x8_kernel(const float* __restrict__ X) {
    int idx = blockIdx.x * blockDim.x + threadIdx.x;
    if (idx >= BATCH * (KP8 / 4)) return;
    int r  = idx / (KP8 / 4);
    int c4 = (idx % (KP8 / 4)) * 4;
    char hq[4], lq[4];
    #pragma unroll
    for (int j = 0; j < 4; ++j) {
        int col = c4 + j;
        float x = (col < IN_F) ? X[(size_t)r * IN_F + col] : 0.0f;
        int Q = __float2int_rn(x * SCALE_S);
        Q = max(-32512, min(32512, Q));
        int Qh = (Q + 128) >> 8;
        int Ql = Q - (Qh << 8);
        hq[j] = (char)Qh;
        lq[j] = (char)Ql;
    }
    *(char4*)(g_Xh8 + (size_t)r * KP8 + c4) = make_char4(hq[0], hq[1], hq[2], hq[3]);
    *(char4*)(g_Xl8 + (size_t)r * KP8 + c4) = make_char4(lq[0], lq[1], lq[2], lq[3]);
}

__global__ void conv_w8_kernel(const float* __restrict__ W1) {
    int idx = blockIdx.x * blockDim.x + threadIdx.x;
    if (idx >= HID * (KP8 / 4)) return;
    int r  = idx / (KP8 / 4);
    int c4 = (idx % (KP8 / 4)) * 4;
    char s[4];
    #pragma unroll
    for (int j = 0; j < 4; ++j) {
        int col = c4 + j;
        char v = 0;
        if (col < IN_F) {
            float w = W1[(size_t)r * IN_F + col];
            v = (w > 0.0f) ? (char)1 : ((w < 0.0f) ? (char)-1 : (char)0);
        }
        s[j] = v;
    }
    *(char4*)(g_W8 + (size_t)r * KP8 + c4) = make_char4(s[0], s[1], s[2], s[3]);
}

// ---------------------------------------------------------------- main
__global__ void __launch_bounds__(256, 2) fused_i8_kernel(
    const float* __restrict__ b1, const float* __restrict__ W2,
    float* __restrict__ out)
{
    extern __shared__ char smem_raw[];
    const uint32_t rawA  = smem_u32(smem_raw);
    const uint32_t sbase = (rawA + 127) & ~127u;
    char* gbase = smem_raw + (sbase - rawA);
    float* W2s = (float*)(gbase + OFF_W2);
    float* b1s = (float*)(gbase + OFF_B1);

    const int tid  = threadIdx.x;
    const int lane = tid & 31;
    const int wid  = tid >> 5;
    const int wm   = wid & 1;        // 2 warps along M (32 rows each)
    const int wn   = wid >> 1;       // 4 warps along N (32 cols each)

    const int bm = blockIdx.y * BM;
    const int bn = blockIdx.x * BN;

    for (int i = tid; i < NOUT * BN; i += 256)
        W2s[i] = W2[(size_t)(i >> 7) * HID + bn + (i & 127)];
    if (tid < BN) b1s[tid] = b1[bn + tid];

    // ---- loader mapping (per chunk: Ahi, Alo, B0, B1 = 4 x 16B / thread) ----
    const int lrow = tid >> 2;           // 0..63
    const int lseg = tid & 3;
    const uint32_t aSw  = sw128((uint32_t)tid * 16);
    const uint32_t bSw0 = aSw;
    const uint32_t bSw1 = sw128((uint32_t)tid * 16 + 4096);
    const char* gXh = g_Xh8 + (size_t)(bm + lrow) * KP8 + lseg * 16;
    const char* gXl = g_Xl8 + (size_t)(bm + lrow) * KP8 + lseg * 16;
    const char* gW0 = g_W8  + (size_t)(bn + lrow) * KP8 + lseg * 16;
    const char* gW1 = g_W8  + (size_t)(bn + 64 + lrow) * KP8 + lseg * 16;

    // ---- ldmatrix per-lane offsets (row stride 64 B, 2 k-steps) ----
    const int lg  = lane >> 3;
    const int lr8 = lane & 7;
    uint32_t aOff[2][2], bOff[2][2];
    #pragma unroll
    for (int mi = 0; mi < 2; ++mi) {
        int r = wm * 32 + mi * 16 + ((lg & 1) << 3) + lr8;
        #pragma unroll
        for (int ks = 0; ks < 2; ++ks)
            aOff[mi][ks] = sw128((uint32_t)(r * 64 + ks * 32 + (lg >> 1) * 16));
    }
    #pragma unroll
    for (int n2 = 0; n2 < 2; ++n2) {
        int r = wn * 32 + n2 * 16 + (((lane >> 4) & 1) << 3) + lr8;
        #pragma unroll
        for (int ks = 0; ks < 2; ++ks)
            bOff[n2][ks] = sw128((uint32_t)(r * 64 + ks * 32 + (lg & 1) * 16));
    }

    int accH[2][4][4], accL[2][4][4];
    #pragma unroll
    for (int mi = 0; mi < 2; ++mi)
        #pragma unroll
        for (int ni = 0; ni < 4; ++ni)
            #pragma unroll
            for (int q = 0; q < 4; ++q) { accH[mi][ni][q] = 0; accL[mi][ni][q] = 0; }

    // ---- preload chunks 0..2 ----
    #pragma unroll
    for (int p = 0; p < 3; ++p) {
        uint32_t dst = sbase + p * STAGE;
        CP_ASYNC16(dst + aSw, gXh + p * BK);
        CP_ASYNC16(dst + OFF_ALO + aSw, gXl + p * BK);
        CP_ASYNC16(dst + OFF_BW + bSw0, gW0 + p * BK);
        CP_ASYNC16(dst + OFF_BW + bSw1, gW1 + p * BK);
        CP_COMMIT();
    }

    for (int kc = 0; kc < NCH; ++kc) {
        const int s = kc & 3;
        if (kc < NCH - 2)       { CP_WAIT(2); }
        else if (kc == NCH - 2) { CP_WAIT(1); }
        else                    { CP_WAIT(0); }
        __syncthreads();

        const uint32_t base = sbase + s * STAGE;

        // ---- issue ALL 12 LDSMs for this chunk up-front (both ks blocks) ----
        uint32_t bb[2][4][2];   // [ks][ni][2]
        uint32_t ah[2][2][4];   // [ks][mi][4]
        uint32_t al[2][2][4];
        #pragma unroll
        for (int ks = 0; ks < 2; ++ks)
            #pragma unroll
            for (int n2 = 0; n2 < 2; ++n2)
                ldm_x4(bb[ks][2 * n2][0], bb[ks][2 * n2][1],
                       bb[ks][2 * n2 + 1][0], bb[ks][2 * n2 + 1][1],
                       base + OFF_BW + bOff[n2][ks]);
        #pragma unroll
        for (int ks = 0; ks < 2; ++ks)
            #pragma unroll
            for (int mi = 0; mi < 2; ++mi)
                ldm_x4(ah[ks][mi][0], ah[ks][mi][1], ah[ks][mi][2], ah[ks][mi][3],
                       base + aOff[mi][ks]);
        #pragma unroll
        for (int ks = 0; ks < 2; ++ks)
            #pragma unroll
            for (int mi = 0; mi < 2; ++mi)
                ldm_x4(al[ks][mi][0], al[ks][mi][1], al[ks][mi][2], al[ks][mi][3],
                       base + OFF_ALO + aOff[mi][ks]);

        // ---- prefetch chunk kc+3 while LDSMs land ----
        if (kc + 3 < NCH) {
            uint32_t dst = sbase + ((kc + 3) & 3) * STAGE;
            CP_ASYNC16(dst + aSw, gXh + (kc + 3) * BK);
            CP_ASYNC16(dst + OFF_ALO + aSw, gXl + (kc + 3) * BK);
            CP_ASYNC16(dst + OFF_BW + bSw0, gW0 + (kc + 3) * BK);
            CP_ASYNC16(dst + OFF_BW + bSw1, gW1 + (kc + 3) * BK);
            CP_COMMIT();
        }

        // ---- IMMA phase: H then L per ks (L's LDSMs land last) ----
        #pragma unroll
        for (int ks = 0; ks < 2; ++ks) {
            #pragma unroll
            for (int mi = 0; mi < 2; ++mi)
                #pragma unroll
                for (int ni = 0; ni < 4; ++ni)
                    MMA_S8(accH[mi][ni], ah[ks][mi], bb[ks][ni]);
            #pragma unroll
            for (int mi = 0; mi < 2; ++mi)
                #pragma unroll
                for (int ni = 0; ni < 4; ++ni)
                    MMA_S8(accL[mi][ni], al[ks][mi], bb[ks][ni]);
        }
    }

    // ---- epilogue: combine planes, bias + hardtanh, fused fc2 ----
    const int dg = lane >> 2;
    const int dt = lane & 3;

    float hv[2][4][4];
    #pragma unroll
    for (int mi = 0; mi < 2; ++mi)
        #pragma unroll
        for (int ni = 0; ni < 4; ++ni)
            #pragma unroll
            for (int q = 0; q < 4; ++q) {
                int n = wn * 32 + ni * 8 + 2 * dt + (q & 1);
                float hf = fmaf(256.0f, (float)accH[mi][ni][q], (float)accL[mi][ni][q]);
                float v  = fmaf(hf, INV_S, b1s[n]);
                hv[mi][ni][q] = fminf(1.0f, fmaxf(-1.0f, v));
            }

    #pragma unroll
    for (int o = 0; o < NOUT; ++o) {
        #pragma unroll
        for (int mi = 0; mi < 2; ++mi) {
            float s0 = 0.0f, s1 = 0.0f;
            #pragma unroll
            for (int ni = 0; ni < 4; ++ni) {
                int n0 = wn * 32 + ni * 8 + 2 * dt;
                float w0 = W2s[o * BN + n0];
                float w1 = W2s[o * BN + n0 + 1];
                s0 = fmaf(hv[mi][ni][0], w0, fmaf(hv[mi][ni][1], w1, s0));
                s1 = fmaf(hv[mi][ni][2], w0, fmaf(hv[mi][ni][3], w1, s1));
            }
            s0 += __shfl_xor_sync(0xffffffffu, s0, 1);
            s0 += __shfl_xor_sync(0xffffffffu, s0, 2);
            s1 += __shfl_xor_sync(0xffffffffu, s1, 1);
            s1 += __shfl_xor_sync(0xffffffffu, s1, 2);
            if (dt == 0) {
                int r0 = bm + wm * 32 + mi * 16 + dg;
                atomicAdd(&out[(size_t)r0 * NOUT + o], s0);
                atomicAdd(&out[(size_t)(r0 + 8) * NOUT + o], s1);
            }
        }
    }
}

// ---------------------------------------------------------------- launch
extern "C" void kernel_launch(void* const* d_in, const int* in_sizes, int n_in,
                              void* d_out, int out_size) {
    const float* X  = (const float*)d_in[0];   // [8192, 784]
    const float* W1 = (const float*)d_in[1];   // [4096, 784]
    const float* b1 = (const float*)d_in[2];   // [4096]
    const float* W2 = (const float*)d_in[3];   // [10, 4096]
    const float* b2 = (const float*)d_in[4];   // [10]
    float* out = (float*)d_out;                // [8192, 10]
    (void)in_sizes; (void)n_in; (void)out_size;

    cudaFuncSetAttribute(fused_i8_kernel,
                         cudaFuncAttributeMaxDynamicSharedMemorySize, SMEM_REQ);

    init_out_kernel<<<(BATCH * NOUT + 255) / 256, 256>>>(out, b2);
    conv_x8_kernel<<<(BATCH * (KP8 / 4) + 255) / 256, 256>>>(X);
    conv_w8_kernel<<<(HID * (KP8 / 4) + 255) / 256, 256>>>(W1);

    dim3 grid(HID / BN, BATCH / BM);   // (32, 128) = 4096 CTAs
    fused_i8_kernel<<<grid, 256, SMEM_REQ>>>(b1, W2, out);
}